// round 9
// baseline (speedup 1.0000x reference)
#include <cuda_runtime.h>
#include <math.h>
#include <float.h>

#define MROWS   4096
#define NCOLS   16384
#define KHARD   163          // int(0.01 * (16384-1))
#define DELTA_W 5.0f
#define THR0    2.0f
#define NT      128
#define NWARP   (NT / 32)
#define QSLOTS  12           // per-thread float4 quad slots
#define NB      512          // linear value bins over [THR0, THR0+4)
#define GCAP    64
#define FULLM   0xFFFFFFFFu

__device__ float    g_partials[MROWS];
__device__ unsigned g_done = 0;

__device__ __forceinline__ unsigned fkey(float x) {
    unsigned b = __float_as_uint(x);
    return (b & 0x80000000u) ? ~b : (b | 0x80000000u);
}
__device__ __forceinline__ float unfkey(unsigned k) {
    return (k & 0x80000000u) ? __uint_as_float(k ^ 0x80000000u) : __uint_as_float(~k);
}
__device__ __forceinline__ float softplus(float x) {
    return fmaxf(x, 0.0f) + log1pf(__expf(-fabsf(x)));
}
__device__ __forceinline__ int binof(float x) {          // x > THR0
    int b = (int)((x - THR0) * 128.0f);                  // NB/4 per unit
    return b > NB - 1 ? NB - 1 : b;
}

// Boundary-bin search for the r-th largest over hist[0..B). Requires B >= NT.
// s_out = {bin, count strictly above bin, bin count}. 2 barriers.
__device__ __forceinline__ void select_bin(const unsigned* __restrict__ hist, int B,
                                           unsigned r, unsigned* s_warpS,
                                           unsigned* s_out)
{
    const int tid = threadIdx.x, lane = tid & 31, wid = tid >> 5;
    const int c = B / NT;
    unsigned total = 0;
    const int base = tid * c;
    for (int j = 0; j < c; ++j) total += hist[base + j];
    unsigned incl = total;
    #pragma unroll
    for (int off = 1; off < 32; off <<= 1) {
        unsigned v = __shfl_down_sync(FULLM, incl, off);
        if (lane + off < 32) incl += v;
    }
    if (lane == 0) s_warpS[wid] = incl;
    __syncthreads();
    unsigned hi = 0;
    #pragma unroll
    for (int w = 0; w < NWARP; ++w) if (w > wid) hi += s_warpS[w];
    unsigned S = incl + hi;
    unsigned above_chunk = S - total;
    if (above_chunk < r && S >= r) {
        unsigned run = above_chunk;
        for (int j = c - 1; j >= 0; --j) {
            unsigned cnt = hist[base + j];
            if (run + cnt >= r) { s_out[0] = base + j; s_out[1] = run; s_out[2] = cnt; break; }
            run += cnt;
        }
    }
    __syncthreads();
}

extern "C" __global__ void __launch_bounds__(NT, 8)
mmcl_kernel(const float* __restrict__ in, const int* __restrict__ tg,
            float* __restrict__ out)
{
    __shared__ float4   qcand[QSLOTS * NT];     // 24 KB, interleaved per-thread quads
    __shared__ unsigned hist[NB];
    __shared__ unsigned s_gn, s_flag;
    __shared__ unsigned s_warpS[NWARP];
    __shared__ unsigned s_out[3];
    __shared__ float    s_red[NWARP];
    __shared__ float    s_gath[GCAP];
    __shared__ float    s_pos, s_bsum;

    const int tid  = threadIdx.x;
    const int lane = tid & 31;
    const int wid  = tid >> 5;
    const int row  = blockIdx.x;

    const float* __restrict__ rowp = in + (size_t)row * NCOLS;
    const int tgt = tg[row];

    for (int i = tid; i < NB / 4; i += NT)
        ((uint4*)hist)[i] = make_uint4(0, 0, 0, 0);
    if (tid == 0) { s_gn = 0; s_pos = rowp[tgt]; }

    // ---- sweep: register-batched loads (MLP=8) + quad-granularity compaction ----
    const float4* __restrict__ p = (const float4*)rowp;
    unsigned q = 0;                              // quads stored by this thread
    #pragma unroll
    for (int g = 0; g < 4; ++g) {                // 4 groups x 8 float4 x 128 thr = 16384
        float4 buf[8];
        #pragma unroll
        for (int j = 0; j < 8; ++j)
            buf[j] = __ldcs(&p[(g * 8 + j) * NT + tid]);
        #pragma unroll
        for (int j = 0; j < 8; ++j) {
            float4 f = buf[j];
            float mx = fmaxf(fmaxf(f.x, f.y), fmaxf(f.z, f.w));
            if (mx > THR0) {
                if (q < QSLOTS) qcand[q * NT + tid] = f;   // one STS.128
                ++q;
            }
        }
    }
    const unsigned qn = q <= QSLOTS ? q : QSLOTS;

    // ---- histogram + true-candidate count from own quads (junk filtered) ----
    unsigned myreal = 0;
    for (unsigned i = 0; i < qn; ++i) {
        float4 f = qcand[i * NT + tid];
        if (f.x > THR0) { ++myreal; atomicAdd(&hist[binof(f.x)], 1u); }
        if (f.y > THR0) { ++myreal; atomicAdd(&hist[binof(f.y)], 1u); }
        if (f.z > THR0) { ++myreal; atomicAdd(&hist[binof(f.z)], 1u); }
        if (f.w > THR0) { ++myreal; atomicAdd(&hist[binof(f.w)], 1u); }
    }
    const unsigned wsum = __reduce_add_sync(FULLM, myreal);
    const unsigned wovf = __ballot_sync(FULLM, q > QSLOTS);
    if (lane == 0) s_warpS[wid] = (wsum << 1) | (wovf ? 1u : 0u);
    __syncthreads();                             // also drains hist atomics
    unsigned nc = 0, ovf = 0;
    #pragma unroll
    for (int w = 0; w < NWARP; ++w) { nc += s_warpS[w] >> 1; ovf |= s_warpS[w] & 1u; }

    const float    pos = s_pos;
    const unsigned pos_in = (pos > THR0) ? 1u : 0u;
    bool gmode = (nc < KHARD + pos_in) || ovf;

    float sum = 0.0f;
    bool use_key = false;
    unsigned tkey = 0, rmul = 0;
    int bbin = NB;

    if (!gmode) {
        if (tid == 0 && pos_in) atomicSub(&hist[binof(pos)], 1u);
        __syncthreads();

        select_bin(hist, NB, KHARD, s_warpS, s_out);
        bbin = (int)s_out[0];
        const unsigned rp = KHARD - s_out[1];    // rank within boundary bin

        // fused pass over OWN quads: strict-above sum + boundary gather
        for (unsigned i = 0; i < qn; ++i) {
            float4 f = qcand[i * NT + tid];
            #pragma unroll
            for (int e = 0; e < 4; ++e) {
                float x = e == 0 ? f.x : e == 1 ? f.y : e == 2 ? f.z : f.w;
                if (x > THR0) {
                    int b = binof(x);
                    if (b > bbin) sum += softplus(x);
                    else if (b == bbin) {
                        unsigned g = atomicAdd(&s_gn, 1u);
                        if (g < GCAP) s_gath[g] = x;
                    }
                }
            }
        }
        __syncthreads();

        if (s_gn > GCAP) { gmode = true; sum = 0.0f; }
        else if (tid == 0) {
            int n = (int)s_gn;
            if (pos_in && binof(pos) == bbin) {  // drop one positive instance
                for (int j = 0; j < n; ++j)
                    if (s_gath[j] == pos) { s_gath[j] = s_gath[n - 1]; --n; break; }
            }
            float bs = 0.0f;                     // top-rp of the boundary bin
            for (int a = 0; a < (int)rp; ++a) {
                int mi = a; float mv = s_gath[a];
                for (int b2 = a + 1; b2 < n; ++b2)
                    if (s_gath[b2] > mv) { mv = s_gath[b2]; mi = b2; }
                s_gath[mi] = s_gath[a]; s_gath[a] = mv;
                bs += softplus(mv);
            }
            s_bsum = bs;
        }
    }

    if (gmode) {
        // exact 4x8-bit fkey radix select from gmem; fires only on slot overflow
        use_key = true;
        unsigned prefix = 0, r = KHARD;
        for (int lev = 0; lev < 4; ++lev) {
            const int shift = 24 - 8 * lev;
            for (int i = tid; i < 256; i += NT) hist[i] = 0;
            __syncthreads();
            for (int j = tid; j < NCOLS; j += NT) {
                if (j == tgt) continue;
                unsigned u = fkey(rowp[j]);
                bool match = (lev == 0) || (((u ^ prefix) >> (shift + 8)) == 0u);
                if (match) atomicAdd(&hist[(u >> shift) & 255u], 1u);
            }
            __syncthreads();
            select_bin(hist, 256, r, s_warpS, s_out);
            prefix |= s_out[0] << shift;
            r -= s_out[1];
            __syncthreads();
        }
        tkey = prefix; rmul = r;
        for (int j = tid; j < NCOLS; j += NT) {
            if (j == tgt) continue;
            float x = rowp[j];
            if (fkey(x) > tkey) sum += softplus(x);
        }
    }

    // ---- block reduce strict sum, write row partial ----
    #pragma unroll
    for (int o = 16; o; o >>= 1) sum += __shfl_down_sync(FULLM, sum, o);
    if (lane == 0) s_red[wid] = sum;
    __syncthreads();

    if (tid == 0) {
        float tot = 0.0f;
        #pragma unroll
        for (int w = 0; w < NWARP; ++w) tot += s_red[w];
        if (!use_key) {
            if (pos_in && binof(pos) > bbin) tot -= softplus(pos);
            tot += s_bsum;
        } else {
            tot += (float)rmul * softplus(unfkey(tkey));
        }
        g_partials[row] = DELTA_W * softplus(-pos) + tot / (float)KHARD;
        __threadfence();
        unsigned old = atomicAdd(&g_done, 1u);
        s_flag = (old == MROWS - 1) ? 1u : 0u;
    }
    __syncthreads();

    if (s_flag) {
        __threadfence();
        float s = 0.0f;
        for (int i = tid; i < MROWS; i += NT) s += __ldcg(&g_partials[i]);
        #pragma unroll
        for (int o = 16; o; o >>= 1) s += __shfl_down_sync(FULLM, s, o);
        if (lane == 0) s_red[wid] = s;
        __syncthreads();
        if (tid == 0) {
            float tot = 0.0f;
            #pragma unroll
            for (int w = 0; w < NWARP; ++w) tot += s_red[w];
            out[0] = tot / (float)MROWS;
            g_done = 0;                          // reset for next graph replay
        }
    }
}

extern "C" void kernel_launch(void* const* d_in, const int* in_sizes, int n_in,
                              void* d_out, int out_size)
{
    const float* in  = (const float*)d_in[0];
    const int*   tg  = (const int*)d_in[1];
    float*       out = (float*)d_out;
    mmcl_kernel<<<MROWS, NT>>>(in, tg, out);
}

// round 10
// speedup vs baseline: 1.2940x; 1.2940x over previous
#include <cuda_runtime.h>
#include <math.h>
#include <float.h>

#define MROWS   4096
#define NCOLS   16384
#define KHARD   163          // int(0.01 * (16384-1))
#define DELTA_W 5.0f
#define THR0    2.0f
#define NT      128
#define NWARP   (NT / 32)
#define SLOTS   16           // per-thread private candidate slots
#define NB      256          // linear value bins over [THR0, THR0+4)
#define GCAP    64
#define FULLM   0xFFFFFFFFu

__device__ float    g_partials[MROWS];
__device__ unsigned g_done = 0;

__device__ __forceinline__ unsigned fkey(float x) {
    unsigned b = __float_as_uint(x);
    return (b & 0x80000000u) ? ~b : (b | 0x80000000u);
}
__device__ __forceinline__ float unfkey(unsigned k) {
    return (k & 0x80000000u) ? __uint_as_float(k ^ 0x80000000u) : __uint_as_float(~k);
}
__device__ __forceinline__ float softplus(float x) {
    return fmaxf(x, 0.0f) + log1pf(__expf(-fabsf(x)));
}
__device__ __forceinline__ int binof(float x) {          // x > THR0
    int b = (int)((x - THR0) * 64.0f);                   // NB/4 per unit
    return b > NB - 1 ? NB - 1 : b;
}

// Boundary-bin search for the r-th largest over hist[0..B). Requires B >= NT.
// s_out = {bin, count strictly above bin, bin count}. 2 barriers.
__device__ __forceinline__ void select_bin(const unsigned* __restrict__ hist, int B,
                                           unsigned r, unsigned* s_warpS,
                                           unsigned* s_out)
{
    const int tid = threadIdx.x, lane = tid & 31, wid = tid >> 5;
    const int c = (B + NT - 1) / NT;
    unsigned total = 0;
    const int base = tid * c;
    for (int j = 0; j < c; ++j)
        if (base + j < B) total += hist[base + j];
    unsigned incl = total;
    #pragma unroll
    for (int off = 1; off < 32; off <<= 1) {
        unsigned v = __shfl_down_sync(FULLM, incl, off);
        if (lane + off < 32) incl += v;
    }
    if (lane == 0) s_warpS[wid] = incl;
    __syncthreads();
    unsigned hi = 0;
    #pragma unroll
    for (int w = 0; w < NWARP; ++w) if (w > wid) hi += s_warpS[w];
    unsigned S = incl + hi;
    unsigned above_chunk = S - total;
    if (above_chunk < r && S >= r) {
        unsigned run = above_chunk;
        for (int j = c - 1; j >= 0; --j) {
            if (base + j >= B) continue;
            unsigned cnt = hist[base + j];
            if (run + cnt >= r) { s_out[0] = base + j; s_out[1] = run; s_out[2] = cnt; break; }
            run += cnt;
        }
    }
    __syncthreads();
}

extern "C" __global__ void __launch_bounds__(NT, 14)
mmcl_kernel(const float* __restrict__ in, const int* __restrict__ tg,
            float* __restrict__ out)
{
    __shared__ float    cand[SLOTS * NT];       // 8 KB, interleaved per-thread segments
    __shared__ unsigned hist[NB];               // 1 KB
    __shared__ unsigned s_gn, s_flag;
    __shared__ unsigned s_warpS[NWARP];
    __shared__ unsigned s_out[3];
    __shared__ float    s_red[NWARP];
    __shared__ float    s_gath[GCAP];
    __shared__ float    s_pos, s_bsum;

    const int tid  = threadIdx.x;
    const int lane = tid & 31;
    const int wid  = tid >> 5;
    const int row  = blockIdx.x;

    const float* __restrict__ rowp = in + (size_t)row * NCOLS;
    const int tgt = tg[row];

    for (int i = tid; i < NB / 4; i += NT)
        ((uint4*)hist)[i] = make_uint4(0, 0, 0, 0);
    if (tid == 0) { s_gn = 0; s_pos = rowp[tgt]; }

    // ---- minimal sweep: private-slot compaction only (no hist, no collectives) ----
    const float4* __restrict__ p = (const float4*)rowp;
    unsigned mycnt = 0;
    #pragma unroll 8
    for (int it = 0; it < NCOLS / 4 / NT; ++it) {        // 32 iterations
        float4 f = __ldcs(&p[it * NT + tid]);
        if (f.x > THR0) { if (mycnt < SLOTS) cand[mycnt * NT + tid] = f.x; ++mycnt; }
        if (f.y > THR0) { if (mycnt < SLOTS) cand[mycnt * NT + tid] = f.y; ++mycnt; }
        if (f.z > THR0) { if (mycnt < SLOTS) cand[mycnt * NT + tid] = f.z; ++mycnt; }
        if (f.w > THR0) { if (mycnt < SLOTS) cand[mycnt * NT + tid] = f.w; ++mycnt; }
    }
    const unsigned wsum = __reduce_add_sync(FULLM, mycnt);
    const unsigned wovf = __ballot_sync(FULLM, mycnt > SLOTS);
    if (lane == 0) s_warpS[wid] = (wsum << 1) | (wovf ? 1u : 0u);
    __syncthreads();
    unsigned nc = 0, ovf = 0;
    #pragma unroll
    for (int w = 0; w < NWARP; ++w) { nc += s_warpS[w] >> 1; ovf |= s_warpS[w] & 1u; }

    const float    pos = s_pos;
    const unsigned pos_in = (pos > THR0) ? 1u : 0u;
    bool gmode = (nc < KHARD + pos_in) || ovf;

    float sum = 0.0f;              // strict-above softplus partial (this thread)
    bool use_key = false;
    unsigned tkey = 0, rmul = 0;
    int bbin = NB;

    if (!gmode) {
        // histogram from own slots (few elements each)
        for (unsigned i = 0; i < mycnt; ++i)
            atomicAdd(&hist[binof(cand[i * NT + tid])], 1u);
        if (tid == 0 && pos_in) atomicSub(&hist[binof(pos)], 1u);
        __syncthreads();

        select_bin(hist, NB, KHARD, s_warpS, s_out);
        bbin = (int)s_out[0];
        const unsigned rp = KHARD - s_out[1];   // rank within boundary bin

        // fused pass over OWN candidates: strict sum + boundary gather
        for (unsigned i = 0; i < mycnt; ++i) {
            float x = cand[i * NT + tid];
            int b = binof(x);
            if (b > bbin) sum += softplus(x);
            else if (b == bbin) {
                unsigned g = atomicAdd(&s_gn, 1u);
                if (g < GCAP) s_gath[g] = x;
            }
        }
        __syncthreads();

        if (s_gn > GCAP) { gmode = true; sum = 0.0f; }
        else if (tid == 0) {
            int n = (int)s_gn;
            if (pos_in && binof(pos) == bbin) {   // drop one positive instance
                for (int j = 0; j < n; ++j)
                    if (s_gath[j] == pos) { s_gath[j] = s_gath[n - 1]; --n; break; }
            }
            float bs = 0.0f;                      // top-rp of the boundary bin
            for (int a = 0; a < (int)rp; ++a) {
                int mi = a; float mv = s_gath[a];
                for (int b2 = a + 1; b2 < n; ++b2)
                    if (s_gath[b2] > mv) { mv = s_gath[b2]; mi = b2; }
                s_gath[mi] = s_gath[a]; s_gath[a] = mv;
                bs += softplus(mv);
            }
            s_bsum = bs;
        }
    }

    if (gmode) {
        // exact 4x8-bit fkey radix select from gmem; never fires for N(0,1)
        use_key = true;
        unsigned prefix = 0, r = KHARD;
        for (int lev = 0; lev < 4; ++lev) {
            const int shift = 24 - 8 * lev;
            for (int i = tid; i < 256; i += NT) hist[i] = 0;
            __syncthreads();
            for (int j = tid; j < NCOLS; j += NT) {
                if (j == tgt) continue;
                unsigned u = fkey(rowp[j]);
                bool match = (lev == 0) || (((u ^ prefix) >> (shift + 8)) == 0u);
                if (match) atomicAdd(&hist[(u >> shift) & 255u], 1u);
            }
            __syncthreads();
            select_bin(hist, 256, r, s_warpS, s_out);
            prefix |= s_out[0] << shift;
            r -= s_out[1];
            __syncthreads();
        }
        tkey = prefix; rmul = r;
        for (int j = tid; j < NCOLS; j += NT) {
            if (j == tgt) continue;
            float x = rowp[j];
            if (fkey(x) > tkey) sum += softplus(x);
        }
    }

    // ---- block reduce strict sum ----
    #pragma unroll
    for (int o = 16; o; o >>= 1) sum += __shfl_down_sync(FULLM, sum, o);
    if (lane == 0) s_red[wid] = sum;
    __syncthreads();

    if (tid == 0) {
        float tot = 0.0f;
        #pragma unroll
        for (int w = 0; w < NWARP; ++w) tot += s_red[w];
        if (!use_key) {
            if (pos_in && binof(pos) > bbin) tot -= softplus(pos);  // pos polluted strict sum
            tot += s_bsum;
        } else {
            tot += (float)rmul * softplus(unfkey(tkey));
        }
        g_partials[row] = DELTA_W * softplus(-pos) + tot / (float)KHARD;
        __threadfence();
        unsigned old = atomicAdd(&g_done, 1u);
        s_flag = (old == MROWS - 1) ? 1u : 0u;
    }
    __syncthreads();

    if (s_flag) {
        __threadfence();
        float s = 0.0f;
        for (int i = tid; i < MROWS; i += NT) s += __ldcg(&g_partials[i]);
        #pragma unroll
        for (int o = 16; o; o >>= 1) s += __shfl_down_sync(FULLM, s, o);
        if (lane == 0) s_red[wid] = s;
        __syncthreads();
        if (tid == 0) {
            float tot = 0.0f;
            #pragma unroll
            for (int w = 0; w < NWARP; ++w) tot += s_red[w];
            out[0] = tot / (float)MROWS;
            g_done = 0;                               // reset for next graph replay
        }
    }
}

extern "C" void kernel_launch(void* const* d_in, const int* in_sizes, int n_in,
                              void* d_out, int out_size)
{
    const float* in  = (const float*)d_in[0];
    const int*   tg  = (const int*)d_in[1];
    float*       out = (float*)d_out;
    mmcl_kernel<<<MROWS, NT>>>(in, tg, out);
}

// round 11
// speedup vs baseline: 1.3263x; 1.0249x over previous
#include <cuda_runtime.h>
#include <math.h>
#include <float.h>

#define MROWS   4096
#define NCOLS   16384
#define KHARD   163          // int(0.01 * (16384-1))
#define DELTA_W 5.0f
#define THR0    2.0f
#define NT      128
#define NWARP   (NT / 32)
#define SLOTS   16           // per-thread private candidate slots
#define NB      256          // linear value bins over [THR0, THR0+4)
#define GCAP    64
#define GRIDSZ  2048         // 2 rows per CTA, single wave at 14 CTAs/SM
#define FULLM   0xFFFFFFFFu

__device__ float    g_partials[MROWS];
__device__ unsigned g_done = 0;

__device__ __forceinline__ unsigned fkey(float x) {
    unsigned b = __float_as_uint(x);
    return (b & 0x80000000u) ? ~b : (b | 0x80000000u);
}
__device__ __forceinline__ float unfkey(unsigned k) {
    return (k & 0x80000000u) ? __uint_as_float(k ^ 0x80000000u) : __uint_as_float(~k);
}
__device__ __forceinline__ float softplus(float x) {
    return fmaxf(x, 0.0f) + log1pf(__expf(-fabsf(x)));
}
__device__ __forceinline__ int binof(float x) {          // x > THR0
    int b = (int)((x - THR0) * 64.0f);                   // NB/4 per unit
    return b > NB - 1 ? NB - 1 : b;
}
__device__ __forceinline__ void prefetch_l2(const float* p) {
    asm volatile("prefetch.global.L2 [%0];" :: "l"(p));
}

// Boundary-bin search for the r-th largest over hist[0..B).
// s_out = {bin, count strictly above bin, bin count}. 2 barriers.
__device__ __forceinline__ void select_bin(const unsigned* __restrict__ hist, int B,
                                           unsigned r, unsigned* s_warpS,
                                           unsigned* s_out)
{
    const int tid = threadIdx.x, lane = tid & 31, wid = tid >> 5;
    const int c = (B + NT - 1) / NT;
    unsigned total = 0;
    const int base = tid * c;
    for (int j = 0; j < c; ++j)
        if (base + j < B) total += hist[base + j];
    unsigned incl = total;
    #pragma unroll
    for (int off = 1; off < 32; off <<= 1) {
        unsigned v = __shfl_down_sync(FULLM, incl, off);
        if (lane + off < 32) incl += v;
    }
    if (lane == 0) s_warpS[wid] = incl;
    __syncthreads();
    unsigned hi = 0;
    #pragma unroll
    for (int w = 0; w < NWARP; ++w) if (w > wid) hi += s_warpS[w];
    unsigned S = incl + hi;
    unsigned above_chunk = S - total;
    if (above_chunk < r && S >= r) {
        unsigned run = above_chunk;
        for (int j = c - 1; j >= 0; --j) {
            if (base + j >= B) continue;
            unsigned cnt = hist[base + j];
            if (run + cnt >= r) { s_out[0] = base + j; s_out[1] = run; s_out[2] = cnt; break; }
            run += cnt;
        }
    }
    __syncthreads();
}

extern "C" __global__ void __launch_bounds__(NT, 14)
mmcl_kernel(const float* __restrict__ in, const int* __restrict__ tg,
            float* __restrict__ out)
{
    __shared__ float    cand[SLOTS * NT];       // 8 KB, interleaved per-thread segments
    __shared__ unsigned hist[NB];               // 1 KB
    __shared__ unsigned s_gn, s_flag;
    __shared__ unsigned s_warpS[NWARP];
    __shared__ unsigned s_out[3];
    __shared__ float    s_red[NWARP];
    __shared__ float    s_gath[GCAP];
    __shared__ float    s_pos, s_bsum;

    const int tid  = threadIdx.x;
    const int lane = tid & 31;
    const int wid  = tid >> 5;

    #pragma unroll 1
    for (int rep = 0; rep < 2; ++rep) {
        const int row = blockIdx.x + rep * GRIDSZ;
        const float* __restrict__ rowp = in + (size_t)row * NCOLS;
        const int tgt = tg[row];

        __syncthreads();                         // protect smem reuse across rows
        for (int i = tid; i < NB / 4; i += NT)
            ((uint4*)hist)[i] = make_uint4(0, 0, 0, 0);
        if (tid == 0) { s_gn = 0; s_pos = rowp[tgt]; }

        // ---- minimal sweep: private-slot compaction only ----
        const float4* __restrict__ p = (const float4*)rowp;
        unsigned mycnt = 0;
        #pragma unroll 8
        for (int it = 0; it < NCOLS / 4 / NT; ++it) {    // 32 iterations
            float4 f = __ldcs(&p[it * NT + tid]);
            if (f.x > THR0) { if (mycnt < SLOTS) cand[mycnt * NT + tid] = f.x; ++mycnt; }
            if (f.y > THR0) { if (mycnt < SLOTS) cand[mycnt * NT + tid] = f.y; ++mycnt; }
            if (f.z > THR0) { if (mycnt < SLOTS) cand[mycnt * NT + tid] = f.z; ++mycnt; }
            if (f.w > THR0) { if (mycnt < SLOTS) cand[mycnt * NT + tid] = f.w; ++mycnt; }
        }

        // ---- fire-and-forget L2 prefetch of the NEXT row (overlaps select below) ----
        if (rep == 0) {
            const float* nxt = in + (size_t)(row + GRIDSZ) * NCOLS;
            #pragma unroll
            for (int j = 0; j < 4; ++j)                   // 4 x 128 thr = 512 lines x 128B
                prefetch_l2(nxt + (j * NT + tid) * 32);
        }

        const unsigned wsum = __reduce_add_sync(FULLM, mycnt);
        const unsigned wovf = __ballot_sync(FULLM, mycnt > SLOTS);
        if (lane == 0) s_warpS[wid] = (wsum << 1) | (wovf ? 1u : 0u);
        __syncthreads();
        unsigned nc = 0, ovf = 0;
        #pragma unroll
        for (int w = 0; w < NWARP; ++w) { nc += s_warpS[w] >> 1; ovf |= s_warpS[w] & 1u; }

        const float    pos = s_pos;
        const unsigned pos_in = (pos > THR0) ? 1u : 0u;
        bool gmode = (nc < KHARD + pos_in) || ovf;

        float sum = 0.0f;
        bool use_key = false;
        unsigned tkey = 0, rmul = 0;
        int bbin = NB;

        if (!gmode) {
            // histogram from own slots (few elements each)
            for (unsigned i = 0; i < mycnt; ++i)
                atomicAdd(&hist[binof(cand[i * NT + tid])], 1u);
            if (tid == 0 && pos_in) atomicSub(&hist[binof(pos)], 1u);
            __syncthreads();

            select_bin(hist, NB, KHARD, s_warpS, s_out);
            bbin = (int)s_out[0];
            const unsigned rp = KHARD - s_out[1];

            // fused pass over OWN candidates: strict sum + boundary gather
            for (unsigned i = 0; i < mycnt; ++i) {
                float x = cand[i * NT + tid];
                int b = binof(x);
                if (b > bbin) sum += softplus(x);
                else if (b == bbin) {
                    unsigned g = atomicAdd(&s_gn, 1u);
                    if (g < GCAP) s_gath[g] = x;
                }
            }
            __syncthreads();

            if (s_gn > GCAP) { gmode = true; sum = 0.0f; }
            else if (tid == 0) {
                int n = (int)s_gn;
                if (pos_in && binof(pos) == bbin) {       // drop one positive instance
                    for (int j = 0; j < n; ++j)
                        if (s_gath[j] == pos) { s_gath[j] = s_gath[n - 1]; --n; break; }
                }
                float bs = 0.0f;                          // top-rp of the boundary bin
                for (int a = 0; a < (int)rp; ++a) {
                    int mi = a; float mv = s_gath[a];
                    for (int b2 = a + 1; b2 < n; ++b2)
                        if (s_gath[b2] > mv) { mv = s_gath[b2]; mi = b2; }
                    s_gath[mi] = s_gath[a]; s_gath[a] = mv;
                    bs += softplus(mv);
                }
                s_bsum = bs;
            }
        }

        if (gmode) {
            // exact 4x8-bit fkey radix select from gmem; never fires for N(0,1)
            use_key = true;
            unsigned prefix = 0, r = KHARD;
            for (int lev = 0; lev < 4; ++lev) {
                const int shift = 24 - 8 * lev;
                for (int i = tid; i < 256; i += NT) hist[i] = 0;
                __syncthreads();
                for (int j = tid; j < NCOLS; j += NT) {
                    if (j == tgt) continue;
                    unsigned u = fkey(rowp[j]);
                    bool match = (lev == 0) || (((u ^ prefix) >> (shift + 8)) == 0u);
                    if (match) atomicAdd(&hist[(u >> shift) & 255u], 1u);
                }
                __syncthreads();
                select_bin(hist, 256, r, s_warpS, s_out);
                prefix |= s_out[0] << shift;
                r -= s_out[1];
                __syncthreads();
            }
            tkey = prefix; rmul = r;
            for (int j = tid; j < NCOLS; j += NT) {
                if (j == tgt) continue;
                float x = rowp[j];
                if (fkey(x) > tkey) sum += softplus(x);
            }
        }

        // ---- block reduce strict sum, write row partial ----
        #pragma unroll
        for (int o = 16; o; o >>= 1) sum += __shfl_down_sync(FULLM, sum, o);
        if (lane == 0) s_red[wid] = sum;
        __syncthreads();

        if (tid == 0) {
            float tot = 0.0f;
            #pragma unroll
            for (int w = 0; w < NWARP; ++w) tot += s_red[w];
            if (!use_key) {
                if (pos_in && binof(pos) > bbin) tot -= softplus(pos);
                tot += s_bsum;
            } else {
                tot += (float)rmul * softplus(unfkey(tkey));
            }
            g_partials[row] = DELTA_W * softplus(-pos) + tot / (float)KHARD;
        }
    }

    // ---- once per CTA: completion handshake; last CTA reduces all rows ----
    __syncthreads();
    if (tid == 0) {
        __threadfence();
        unsigned old = atomicAdd(&g_done, 1u);
        s_flag = (old == GRIDSZ - 1) ? 1u : 0u;
    }
    __syncthreads();

    if (s_flag) {
        __threadfence();
        float s = 0.0f;
        for (int i = tid; i < MROWS; i += NT) s += __ldcg(&g_partials[i]);
        #pragma unroll
        for (int o = 16; o; o >>= 1) s += __shfl_down_sync(FULLM, s, o);
        if (lane == 0) s_red[wid] = s;
        __syncthreads();
        if (tid == 0) {
            float tot = 0.0f;
            #pragma unroll
            for (int w = 0; w < NWARP; ++w) tot += s_red[w];
            out[0] = tot / (float)MROWS;
            g_done = 0;                               // reset for next graph replay
        }
    }
}

extern "C" void kernel_launch(void* const* d_in, const int* in_sizes, int n_in,
                              void* d_out, int out_size)
{
    const float* in  = (const float*)d_in[0];
    const int*   tg  = (const int*)d_in[1];
    float*       out = (float*)d_out;
    mmcl_kernel<<<GRIDSZ, NT>>>(in, tg, out);
}